// round 7
// baseline (speedup 1.0000x reference)
#include <cuda_runtime.h>
#include <cuda_fp16.h>
#include <cstdint>
#include <math.h>

// Problem constants
#define B_  32
#define T_  256
#define H_  1024
#define G4  4096
#define K_  1024
#define M_  (B_*T_)       // 8192
#define NCTA 128

// ---------------- device scratch ----------------
__device__ __half g_xh [M_*K_];       // fp16 x
__device__ __half g_Wih0[G4*K_];      // fp16 Wih0
__device__ float  g_ih [M_*G4];       // layer-0 input projection (fp32)
__device__ __half g_h0A[B_*H_];
__device__ __half g_h0B[B_*H_];
__device__ __half g_h1A[B_*H_];
__device__ __half g_h1B[B_*H_];
__device__ unsigned g_bar;

// ---------------- ptx helpers ----------------
__device__ __forceinline__ void mma_f16(float* c, const uint32_t* a, const uint32_t* b) {
    asm volatile(
        "mma.sync.aligned.m16n8k16.row.col.f32.f16.f16.f32 "
        "{%0,%1,%2,%3}, {%4,%5,%6,%7}, {%8,%9}, {%0,%1,%2,%3};\n"
        : "+f"(c[0]), "+f"(c[1]), "+f"(c[2]), "+f"(c[3])
        : "r"(a[0]), "r"(a[1]), "r"(a[2]), "r"(a[3]), "r"(b[0]), "r"(b[1]));
}

__device__ __forceinline__ void ldsm_x4(uint32_t& r0, uint32_t& r1, uint32_t& r2, uint32_t& r3,
                                        uint32_t addr) {
    asm volatile("ldmatrix.sync.aligned.m8n8.x4.shared.b16 {%0,%1,%2,%3}, [%4];"
                 : "=r"(r0), "=r"(r1), "=r"(r2), "=r"(r3) : "r"(addr));
}

#define CP_ASYNC_CG(dst, src) \
    asm volatile("cp.async.cg.shared.global [%0], [%1], 16;\n" :: "r"(dst), "l"(src))
#define CP_COMMIT() asm volatile("cp.async.commit_group;\n" ::: "memory")
#define CP_WAIT(N)  asm volatile("cp.async.wait_group %0;\n" :: "n"(N) : "memory")

__device__ __forceinline__ float sig_f(float x) {
    return __fdividef(1.f, 1.f + __expf(-x));
}
__device__ __forceinline__ float tanh_f(float x) {
    float e = __expf(2.f * x);
    return 1.f - __fdividef(2.f, e + 1.f);
}

// ---------------- fp32 -> fp16 conversion ----------------
__global__ void round_half_kernel(const float* __restrict__ src, int n, int dsel) {
    __half* dst = (dsel == 0) ? g_xh : g_Wih0;
    int i4 = (blockIdx.x * blockDim.x + threadIdx.x) * 4;
    if (i4 < n) {
        float4 v = *(const float4*)(src + i4);
        *(__half2*)(dst + i4)     = __floats2half2_rn(v.x, v.y);
        *(__half2*)(dst + i4 + 2) = __floats2half2_rn(v.z, v.w);
    }
}

// ---------------- input projection GEMM (layer 0 only) ----------------
#define BM 128
#define BN 128
#define BKH 32
#define GSTR 40

__global__ __launch_bounds__(256, 2)
void gemm_ih_kernel(const float* __restrict__ bias) {
    const __half* A = g_xh;
    const __half* W = g_Wih0;

    __shared__ __half As[2][BM * GSTR];
    __shared__ __half Bs[2][BM * GSTR];

    int tid  = threadIdx.x;
    int bm   = blockIdx.y * BM;
    int bn   = blockIdx.x * BN;
    int warp = tid >> 5, lane = tid & 31;
    int gid  = lane >> 2, tig = lane & 3;
    int wm   = (warp & 3) * 32;
    int wn   = (warp >> 2) * 64;

    uint32_t sa = (uint32_t)__cvta_generic_to_shared(&As[0][0]);
    uint32_t sb = (uint32_t)__cvta_generic_to_shared(&Bs[0][0]);
    const uint32_t STAGE = BM * GSTR * 2;

    int r0   = tid >> 2;
    int gcol = (tid & 3) * 8;
    const __half* Ap = A + (size_t)(bm + r0) * K_ + gcol;
    const __half* Wp = W + (size_t)(bn + r0) * K_ + gcol;
    uint32_t da0 = sa + (uint32_t)(r0 * GSTR + gcol) * 2;
    uint32_t da1 = sa + (uint32_t)((r0 + 64) * GSTR + gcol) * 2;
    uint32_t db0 = sb + (uint32_t)(r0 * GSTR + gcol) * 2;
    uint32_t db1 = sb + (uint32_t)((r0 + 64) * GSTR + gcol) * 2;

    uint32_t a_off = (uint32_t)(((lane & 7) + ((lane >> 3) & 1) * 8) * GSTR + (lane >> 4) * 8) * 2;
    uint32_t b_off = (uint32_t)(((lane & 7) + ((lane >> 4) & 1) * 8) * GSTR + ((lane >> 3) & 1) * 8) * 2;

    float c[2][8][4];
#pragma unroll
    for (int i = 0; i < 2; i++)
#pragma unroll
        for (int j = 0; j < 8; j++)
#pragma unroll
            for (int q = 0; q < 4; q++) c[i][j][q] = 0.f;

    CP_ASYNC_CG(da0, Ap);
    CP_ASYNC_CG(da1, Ap + (size_t)64 * K_);
    CP_ASYNC_CG(db0, Wp);
    CP_ASYNC_CG(db1, Wp + (size_t)64 * K_);
    CP_COMMIT();

    const int NIT = K_ / BKH;
    for (int it = 0; it < NIT; it++) {
        if (it + 1 < NIT) {
            int k = (it + 1) * BKH;
            uint32_t so = ((it + 1) & 1) * STAGE;
            CP_ASYNC_CG(da0 + so, Ap + k);
            CP_ASYNC_CG(da1 + so, Ap + (size_t)64 * K_ + k);
            CP_ASYNC_CG(db0 + so, Wp + k);
            CP_ASYNC_CG(db1 + so, Wp + (size_t)64 * K_ + k);
            CP_COMMIT();
            CP_WAIT(1);
        } else {
            CP_COMMIT();
            CP_WAIT(0);
        }
        __syncthreads();

        uint32_t sAs = sa + (it & 1) * STAGE;
        uint32_t sBs = sb + (it & 1) * STAGE;
#pragma unroll
        for (int ks = 0; ks < 2; ks++) {
            uint32_t af[2][4], bf[8][2];
#pragma unroll
            for (int mi = 0; mi < 2; mi++)
                ldsm_x4(af[mi][0], af[mi][1], af[mi][2], af[mi][3],
                        sAs + (uint32_t)((wm + mi * 16) * GSTR) * 2 + a_off + ks * 32);
#pragma unroll
            for (int nj = 0; nj < 4; nj++)
                ldsm_x4(bf[2 * nj][0], bf[2 * nj][1], bf[2 * nj + 1][0], bf[2 * nj + 1][1],
                        sBs + (uint32_t)((wn + nj * 16) * GSTR) * 2 + b_off + ks * 32);
#pragma unroll
            for (int mi = 0; mi < 2; mi++)
#pragma unroll
                for (int nj = 0; nj < 8; nj++)
                    mma_f16(c[mi][nj], af[mi], bf[nj]);
        }
        __syncthreads();
    }

#pragma unroll
    for (int mi = 0; mi < 2; mi++) {
#pragma unroll
        for (int nj = 0; nj < 8; nj++) {
            int m0 = bm + wm + mi * 16 + gid;
            int n0 = bn + wn + nj * 8 + 2 * tig;
            float b0v = bias[n0], b1v = bias[n0 + 1];
            size_t o = (size_t)m0 * G4 + n0;
            g_ih[o]                      = c[mi][nj][0] + b0v;
            g_ih[o + 1]                  = c[mi][nj][1] + b1v;
            g_ih[o + (size_t)8 * G4]     = c[mi][nj][2] + b0v;
            g_ih[o + (size_t)8 * G4 + 1] = c[mi][nj][3] + b1v;
        }
    }
}

// ---------------- zero h / barrier ----------------
__global__ void zero_state_kernel() {
    int i = blockIdx.x * blockDim.x + threadIdx.x;
    if (i < B_ * H_) {
        __half z = __float2half(0.f);
        g_h0A[i] = z; g_h0B[i] = z; g_h1A[i] = z; g_h1B[i] = z;
    }
    if (i == 0) g_bar = 0u;
}

// ---------------- fused 2-layer pipelined persistent kernel ----------------
// 512 threads = 16 warps = 2(m16) x 2(n16) x 4(k-quarter).
// Global step s (0..256):
//   pass1: layer0 rec t=s      (Whh0 in REGISTERS, A = staged h0_{s-1})
//   pass2: ih1_{s-1}           (Wih1 in SMEM, SAME A fragments as pass1)
//   pass3: layer1 rec t=s-1    (Whh1 in SMEM, A = staged h1_{s-2})
#define HSTR 1032
#define PSZ  (32 * 33)
#define PERSIST_SMEM (3 * 32 * HSTR * 2 + 4 * PSZ * 4)

__global__ __launch_bounds__(512, 1)
void lstm_fused_kernel(const float* __restrict__ Whh0_raw,
                       const float* __restrict__ Wih1_raw,
                       const float* __restrict__ Whh1_raw,
                       const float* __restrict__ b1_raw,
                       float* __restrict__ out_ext)
{
    extern __shared__ __half smh[];
    __half* Hsm   = smh;                        // 32 x 1032 (h stage; also W bootstrap)
    __half* Wih1s = Hsm + 32 * HSTR;            // 32 x 1032
    __half* Whh1s = Wih1s + 32 * HSTR;          // 32 x 1032
    float*  Ps    = (float*)(Whh1s + 32 * HSTR);

    int tid  = threadIdx.x;
    int warp = tid >> 5, lane = tid & 31;
    int gid  = lane >> 2, tig = lane & 3;
    int mi   = warp & 1;
    int nj   = (warp >> 1) & 1;
    int kq   = warp >> 2;
    int j0   = blockIdx.x * 8;

    uint32_t hs_base = (uint32_t)__cvta_generic_to_shared(Hsm);
    uint32_t w2_base = (uint32_t)__cvta_generic_to_shared(Wih1s);
    uint32_t w3_base = (uint32_t)__cvta_generic_to_shared(Whh1s);

    // ---- helper offsets ----
    uint32_t a_off = (uint32_t)((mi * 16 + (lane & 7) + ((lane >> 3) & 1) * 8) * HSTR +
                                (lane >> 4) * 8 + kq * 256) * 2;
    uint32_t b_off = (uint32_t)((nj * 16 + (lane & 7) + ((lane >> 4) & 1) * 8) * HSTR +
                                ((lane >> 3) & 1) * 8 + kq * 256) * 2;

    // ---- stage Whh0 into Hsm, then ldsm into registers (held all steps) ----
#pragma unroll 4
    for (int i = 0; i < 16; i++) {
        int idx = i * 512 + tid;
        int r   = idx >> 8;
        int c4  = idx & 255;
        int g   = r >> 3, jr = r & 7;
        const float4 v = *(const float4*)(Whh0_raw + ((size_t)(g * H_ + j0 + jr)) * K_ + c4 * 4);
        *(__half2*)&Hsm[r * HSTR + c4 * 4]     = __floats2half2_rn(v.x, v.y);
        *(__half2*)&Hsm[r * HSTR + c4 * 4 + 2] = __floats2half2_rn(v.z, v.w);
    }
    __syncthreads();
    uint32_t bfr[16][4];
#pragma unroll
    for (int ks = 0; ks < 16; ks++)
        ldsm_x4(bfr[ks][0], bfr[ks][1], bfr[ks][2], bfr[ks][3],
                hs_base + b_off + ks * 32);
    __syncthreads();   // done reading Hsm before it becomes the h buffer

    // ---- stage Wih1, Whh1 into SMEM (resident all steps) ----
#pragma unroll 4
    for (int i = 0; i < 16; i++) {
        int idx = i * 512 + tid;
        int r   = idx >> 8;
        int c4  = idx & 255;
        int g   = r >> 3, jr = r & 7;
        size_t wrow = ((size_t)(g * H_ + j0 + jr)) * K_ + c4 * 4;
        float4 v2 = *(const float4*)(Wih1_raw + wrow);
        *(__half2*)&Wih1s[r * HSTR + c4 * 4]     = __floats2half2_rn(v2.x, v2.y);
        *(__half2*)&Wih1s[r * HSTR + c4 * 4 + 2] = __floats2half2_rn(v2.z, v2.w);
        float4 v3 = *(const float4*)(Whh1_raw + wrow);
        *(__half2*)&Whh1s[r * HSTR + c4 * 4]     = __floats2half2_rn(v3.x, v3.y);
        *(__half2*)&Whh1s[r * HSTR + c4 * 4 + 2] = __floats2half2_rn(v3.z, v3.w);
    }

    // h staging indices (512 threads: 8 x 16B each)
    int hr_ = tid >> 4;
    int hc_ = (tid & 15) * 64;
    uint32_t hdst = hs_base + (uint32_t)(hr_ * HSTR + hc_) * 2;

    int b  = tid >> 3;     // gate threads (tid < 256): batch
    int jj = tid & 7;
    float c0 = 0.f, c1 = 0.f;
    float* Pk = Ps + kq * PSZ;

    // bias for layer 1 (per gate thread)
    float b1v0 = 0.f, b1v1 = 0.f, b1v2 = 0.f, b1v3 = 0.f;
    float ih0 = 0.f, ih1v = 0.f, ih2v = 0.f, ih3v = 0.f;
    if (tid < 256) {
        b1v0 = b1_raw[j0 + jj];
        b1v1 = b1_raw[H_ + j0 + jj];
        b1v2 = b1_raw[2 * H_ + j0 + jj];
        b1v3 = b1_raw[3 * H_ + j0 + jj];
        size_t ihb = ((size_t)b * T_) * G4 + j0 + jj;
        ih0  = __ldcs(&g_ih[ihb]);
        ih1v = __ldcs(&g_ih[ihb + H_]);
        ih2v = __ldcs(&g_ih[ihb + 2 * H_]);
        ih3v = __ldcs(&g_ih[ihb + 3 * H_]);
    }
    __syncthreads();

    for (int s = 0; s <= T_; s++) {
        const __half* h0in = ((s + 1) & 1) ? g_h0B : g_h0A;  // h0_{s-1}
        __half*       h0out = (s & 1) ? g_h0B : g_h0A;       // h0_s
        const __half* h1in = (s & 1) ? g_h1B : g_h1A;        // h1_{s-2}
        __half*       h1out = ((s + 1) & 1) ? g_h1B : g_h1A; // h1_{s-1}

        // ---- stage h0_{s-1} (register one-shot) ----
        {
            uint4 rv[8];
            const __half* src = h0in + (size_t)hr_ * H_ + hc_;
#pragma unroll
            for (int i = 0; i < 8; i++)
                rv[i] = __ldcg((const uint4*)(src + i * 8));
#pragma unroll
            for (int i = 0; i < 8; i++)
                *(uint4*)&Hsm[hr_ * HSTR + hc_ + i * 8] = rv[i];
        }
        __syncthreads();

        // ---- pass1 + pass2: shared A fragments ----
        float p1a[4] = {0.f,0.f,0.f,0.f}, p1b[4] = {0.f,0.f,0.f,0.f};
        float p2a[4] = {0.f,0.f,0.f,0.f}, p2b[4] = {0.f,0.f,0.f,0.f};
        {
            uint32_t aaddr = hs_base + a_off;
            uint32_t baddr = w2_base + b_off;
#pragma unroll
            for (int ks = 0; ks < 16; ks++) {
                uint32_t af[4], b2[4];
                ldsm_x4(af[0], af[1], af[2], af[3], aaddr);
                ldsm_x4(b2[0], b2[1], b2[2], b2[3], baddr);
                mma_f16(p1a, af, &bfr[ks][0]);
                mma_f16(p1b, af, &bfr[ks][2]);
                mma_f16(p2a, af, &b2[0]);
                mma_f16(p2b, af, &b2[2]);
                aaddr += 32;
                baddr += 32;
            }
        }

        // scatter pass1
        {
            int m = mi * 16 + gid;
            int n = nj * 16 + 2 * tig;
            Pk[m * 33 + n]           = p1a[0];
            Pk[m * 33 + n + 1]       = p1a[1];
            Pk[(m + 8) * 33 + n]     = p1a[2];
            Pk[(m + 8) * 33 + n + 1] = p1a[3];
            Pk[m * 33 + n + 8]       = p1b[0];
            Pk[m * 33 + n + 9]       = p1b[1];
            Pk[(m + 8) * 33 + n + 8] = p1b[2];
            Pk[(m + 8) * 33 + n + 9] = p1b[3];
        }
        __syncthreads();

        // issue cp.async staging of h1_{s-2} (hidden under gate0 / scatter2)
        {
            const __half* src1 = h1in + (size_t)hr_ * H_ + hc_;
#pragma unroll
            for (int i = 0; i < 8; i++)
                CP_ASYNC_CG(hdst + (uint32_t)(i * 8) * 2, src1 + i * 8);
            CP_COMMIT();
        }

        // gate0: layer0 t=s
        if (s < T_ && tid < 256) {
            const float* P0 = Ps;
            const float* P1 = Ps + PSZ;
            const float* P2 = Ps + 2 * PSZ;
            const float* P3 = Ps + 3 * PSZ;
            int o0 = b * 33 + jj;
            float ipre = P0[o0]      + P1[o0]      + P2[o0]      + P3[o0]      + ih0;
            float fpre = P0[o0 + 8]  + P1[o0 + 8]  + P2[o0 + 8]  + P3[o0 + 8]  + ih1v;
            float gpre = P0[o0 + 16] + P1[o0 + 16] + P2[o0 + 16] + P3[o0 + 16] + ih2v;
            float opre = P0[o0 + 24] + P1[o0 + 24] + P2[o0 + 24] + P3[o0 + 24] + ih3v;
            float iv = sig_f(ipre);
            float fv = sig_f(fpre);
            float gv = tanh_f(gpre);
            float ov = sig_f(opre);
            c0 = fv * c0 + iv * gv;
            float hv = ov * tanh_f(c0);
            __half hr = __float2half_rn(hv);
            unsigned short hb16 = __half_as_ushort(hr);
            asm volatile("st.global.cg.u16 [%0], %1;"
                         :: "l"(h0out + b * H_ + j0 + jj), "h"(hb16) : "memory");
        }
        __syncthreads();   // gate0 done reading Ps

        // scatter pass2
        {
            int m = mi * 16 + gid;
            int n = nj * 16 + 2 * tig;
            Pk[m * 33 + n]           = p2a[0];
            Pk[m * 33 + n + 1]       = p2a[1];
            Pk[(m + 8) * 33 + n]     = p2a[2];
            Pk[(m + 8) * 33 + n + 1] = p2a[3];
            Pk[m * 33 + n + 8]       = p2b[0];
            Pk[m * 33 + n + 9]       = p2b[1];
            Pk[(m + 8) * 33 + n + 8] = p2b[2];
            Pk[(m + 8) * 33 + n + 9] = p2b[3];
        }
        __syncthreads();

        // reduce pass2 -> ih1 (layer-1 input pre-acts for t=s-1)
        float i1_0 = 0.f, i1_1 = 0.f, i1_2 = 0.f, i1_3 = 0.f;
        if (tid < 256) {
            const float* P0 = Ps;
            const float* P1 = Ps + PSZ;
            const float* P2 = Ps + 2 * PSZ;
            const float* P3 = Ps + 3 * PSZ;
            int o0 = b * 33 + jj;
            i1_0 = P0[o0]      + P1[o0]      + P2[o0]      + P3[o0]      + b1v0;
            i1_1 = P0[o0 + 8]  + P1[o0 + 8]  + P2[o0 + 8]  + P3[o0 + 8]  + b1v1;
            i1_2 = P0[o0 + 16] + P1[o0 + 16] + P2[o0 + 16] + P3[o0 + 16] + b1v2;
            i1_3 = P0[o0 + 24] + P1[o0 + 24] + P2[o0 + 24] + P3[o0 + 24] + b1v3;
        }

        // ---- pass3: layer1 recurrence on h1_{s-2} ----
        CP_WAIT(0);
        __syncthreads();
        float p3a[4] = {0.f,0.f,0.f,0.f}, p3b[4] = {0.f,0.f,0.f,0.f};
        {
            uint32_t aaddr = hs_base + a_off;
            uint32_t baddr = w3_base + b_off;
#pragma unroll
            for (int ks = 0; ks < 16; ks++) {
                uint32_t af[4], b3[4];
                ldsm_x4(af[0], af[1], af[2], af[3], aaddr);
                ldsm_x4(b3[0], b3[1], b3[2], b3[3], baddr);
                mma_f16(p3a, af, &b3[0]);
                mma_f16(p3b, af, &b3[2]);
                aaddr += 32;
                baddr += 32;
            }
        }

        // scatter pass3 (Ps reusable: pass2 readers done at CP_WAIT sync)
        {
            int m = mi * 16 + gid;
            int n = nj * 16 + 2 * tig;
            Pk[m * 33 + n]           = p3a[0];
            Pk[m * 33 + n + 1]       = p3a[1];
            Pk[(m + 8) * 33 + n]     = p3a[2];
            Pk[(m + 8) * 33 + n + 1] = p3a[3];
            Pk[m * 33 + n + 8]       = p3b[0];
            Pk[m * 33 + n + 9]       = p3b[1];
            Pk[(m + 8) * 33 + n + 8] = p3b[2];
            Pk[(m + 8) * 33 + n + 9] = p3b[3];
        }
        __syncthreads();

        // gate1: layer1 t=s-1
        float hv1 = 0.f;
        if (s >= 1 && tid < 256) {
            const float* P0 = Ps;
            const float* P1 = Ps + PSZ;
            const float* P2 = Ps + 2 * PSZ;
            const float* P3 = Ps + 3 * PSZ;
            int o0 = b * 33 + jj;
            float ipre = P0[o0]      + P1[o0]      + P2[o0]      + P3[o0]      + i1_0;
            float fpre = P0[o0 + 8]  + P1[o0 + 8]  + P2[o0 + 8]  + P3[o0 + 8]  + i1_1;
            float gpre = P0[o0 + 16] + P1[o0 + 16] + P2[o0 + 16] + P3[o0 + 16] + i1_2;
            float opre = P0[o0 + 24] + P1[o0 + 24] + P2[o0 + 24] + P3[o0 + 24] + i1_3;
            float iv = sig_f(ipre);
            float fv = sig_f(fpre);
            float gv = tanh_f(gpre);
            float ov = sig_f(opre);
            c1 = fv * c1 + iv * gv;
            hv1 = ov * tanh_f(c1);
            __half hr = __float2half_rn(hv1);
            unsigned short hb16 = __half_as_ushort(hr);
            asm volatile("st.global.cg.u16 [%0], %1;"
                         :: "l"(h1out + b * H_ + j0 + jj), "h"(hb16) : "memory");
        }

        // ---- split grid barrier ----
        __threadfence();
        __syncthreads();
        if (tid == 0) atomicAdd(&g_bar, 1u);

        // hidden under barrier wait: out store + next-step ih0 prefetch
        if (tid < 256) {
            if (s >= 1) {
                size_t oidx = ((size_t)(b * T_ + (s - 1))) * H_ + j0 + jj;
                out_ext[oidx] = hv1;
            }
            if (s + 1 < T_) {
                size_t ihn = ((size_t)(b * T_ + s + 1)) * G4 + j0 + jj;
                ih0  = __ldcs(&g_ih[ihn]);
                ih1v = __ldcs(&g_ih[ihn + H_]);
                ih2v = __ldcs(&g_ih[ihn + 2 * H_]);
                ih3v = __ldcs(&g_ih[ihn + 3 * H_]);
            }
        }

        if (tid == 0) {
            unsigned target = (unsigned)NCTA * (unsigned)(s + 1);
            unsigned v;
            do {
                asm volatile("ld.acquire.gpu.global.u32 %0, [%1];" : "=r"(v) : "l"(&g_bar));
            } while (v < target);
        }
        __syncthreads();
    }
}

// ---------------- launch ----------------
extern "C" void kernel_launch(void* const* d_in, const int* in_sizes, int n_in,
                              void* d_out, int out_size) {
    const float* x    = (const float*)d_in[0];
    const float* Wih0 = (const float*)d_in[1];
    const float* Whh0 = (const float*)d_in[2];
    const float* b0   = (const float*)d_in[3];
    const float* Wih1 = (const float*)d_in[4];
    const float* Whh1 = (const float*)d_in[5];
    const float* b1   = (const float*)d_in[6];
    float* out = (float*)d_out;

    static int smem_set = 0;
    if (!smem_set) {
        cudaFuncSetAttribute(lstm_fused_kernel,
                             cudaFuncAttributeMaxDynamicSharedMemorySize, PERSIST_SMEM);
        smem_set = 1;
    }

    const int nx = M_ * K_;
    const int nw = G4 * K_;
    round_half_kernel<<<(nx / 4 + 255) / 256, 256>>>(x,    nx, 0);
    round_half_kernel<<<(nw / 4 + 255) / 256, 256>>>(Wih0, nw, 1);

    dim3 ggrid(G4 / BN, M_ / BM);   // (32, 64)
    gemm_ih_kernel<<<ggrid, 256>>>(b0);
    zero_state_kernel<<<(B_ * H_ + 1023) / 1024, 1024>>>();
    lstm_fused_kernel<<<NCTA, 512, PERSIST_SMEM>>>(Whh0, Wih1, Whh1, b1, out);
}

// round 8
// speedup vs baseline: 1.4377x; 1.4377x over previous
#include <cuda_runtime.h>
#include <cuda_fp16.h>
#include <cstdint>
#include <math.h>

// Problem constants
#define B_  32
#define T_  256
#define H_  1024
#define G4  4096
#define K_  1024
#define M_  (B_*T_)       // 8192
#define NCTA 128

// ---------------- device scratch ----------------
__device__ __half g_xh [M_*K_];       // fp16 x
__device__ __half g_Wh [2*G4*K_];     // fp16 Wih0, Wih1
__device__ float  g_ih [M_*G4];       // input projection (fp32)
__device__ __half g_y1h[M_*H_];       // layer-0 output (fp16)
__device__ __half g_hA [B_*H_];
__device__ __half g_hB [B_*H_];
__device__ unsigned g_bar;

// ---------------- ptx helpers ----------------
__device__ __forceinline__ void mma_f16(float* c, const uint32_t* a, const uint32_t* b) {
    asm volatile(
        "mma.sync.aligned.m16n8k16.row.col.f32.f16.f16.f32 "
        "{%0,%1,%2,%3}, {%4,%5,%6,%7}, {%8,%9}, {%0,%1,%2,%3};\n"
        : "+f"(c[0]), "+f"(c[1]), "+f"(c[2]), "+f"(c[3])
        : "r"(a[0]), "r"(a[1]), "r"(a[2]), "r"(a[3]), "r"(b[0]), "r"(b[1]));
}

__device__ __forceinline__ void ldsm_x4(uint32_t& r0, uint32_t& r1, uint32_t& r2, uint32_t& r3,
                                        uint32_t addr) {
    asm volatile("ldmatrix.sync.aligned.m8n8.x4.shared.b16 {%0,%1,%2,%3}, [%4];"
                 : "=r"(r0), "=r"(r1), "=r"(r2), "=r"(r3) : "r"(addr));
}

#define CP_ASYNC_CG(dst, src) \
    asm volatile("cp.async.cg.shared.global [%0], [%1], 16;\n" :: "r"(dst), "l"(src))
#define CP_COMMIT() asm volatile("cp.async.commit_group;\n" ::: "memory")
#define CP_WAIT(N)  asm volatile("cp.async.wait_group %0;\n" :: "n"(N) : "memory")

__device__ __forceinline__ float sig_f(float x) {
    return __fdividef(1.f, 1.f + __expf(-x));
}
__device__ __forceinline__ float tanh_f(float x) {
    float e = __expf(2.f * x);
    return 1.f - __fdividef(2.f, e + 1.f);
}

// ---------------- fp32 -> fp16 conversion ----------------
__global__ void round_half_kernel(const float* __restrict__ src, int n, int dsel) {
    __half* dst = (dsel == 0) ? g_xh : (g_Wh + (size_t)(dsel - 1) * (G4 * K_));
    int i4 = (blockIdx.x * blockDim.x + threadIdx.x) * 4;
    if (i4 < n) {
        float4 v = *(const float4*)(src + i4);
        *(__half2*)(dst + i4)     = __floats2half2_rn(v.x, v.y);
        *(__half2*)(dst + i4 + 2) = __floats2half2_rn(v.z, v.w);
    }
}

// ---------------- input projection GEMM (cp.async + ldmatrix, 2 CTAs/SM) ----------------
#define BM 128
#define BN 128
#define BKH 32
#define GSTR 40

__global__ __launch_bounds__(256, 2)
void gemm_ih_kernel(int asel, int woff, const float* __restrict__ bias) {
    const __half* A = asel ? g_y1h : g_xh;
    const __half* W = g_Wh + (size_t)woff * (G4 * K_);

    __shared__ __half As[2][BM * GSTR];
    __shared__ __half Bs[2][BM * GSTR];

    int tid  = threadIdx.x;
    int bm   = blockIdx.y * BM;
    int bn   = blockIdx.x * BN;
    int warp = tid >> 5, lane = tid & 31;
    int gid  = lane >> 2, tig = lane & 3;
    int wm   = (warp & 3) * 32;
    int wn   = (warp >> 2) * 64;

    uint32_t sa = (uint32_t)__cvta_generic_to_shared(&As[0][0]);
    uint32_t sb = (uint32_t)__cvta_generic_to_shared(&Bs[0][0]);
    const uint32_t STAGE = BM * GSTR * 2;

    int r0   = tid >> 2;
    int gcol = (tid & 3) * 8;
    const __half* Ap = A + (size_t)(bm + r0) * K_ + gcol;
    const __half* Wp = W + (size_t)(bn + r0) * K_ + gcol;
    uint32_t da0 = sa + (uint32_t)(r0 * GSTR + gcol) * 2;
    uint32_t da1 = sa + (uint32_t)((r0 + 64) * GSTR + gcol) * 2;
    uint32_t db0 = sb + (uint32_t)(r0 * GSTR + gcol) * 2;
    uint32_t db1 = sb + (uint32_t)((r0 + 64) * GSTR + gcol) * 2;

    uint32_t a_off = (uint32_t)(((lane & 7) + ((lane >> 3) & 1) * 8) * GSTR + (lane >> 4) * 8) * 2;
    uint32_t b_off = (uint32_t)(((lane & 7) + ((lane >> 4) & 1) * 8) * GSTR + ((lane >> 3) & 1) * 8) * 2;

    float c[2][8][4];
#pragma unroll
    for (int i = 0; i < 2; i++)
#pragma unroll
        for (int j = 0; j < 8; j++)
#pragma unroll
            for (int q = 0; q < 4; q++) c[i][j][q] = 0.f;

    CP_ASYNC_CG(da0, Ap);
    CP_ASYNC_CG(da1, Ap + (size_t)64 * K_);
    CP_ASYNC_CG(db0, Wp);
    CP_ASYNC_CG(db1, Wp + (size_t)64 * K_);
    CP_COMMIT();

    const int NIT = K_ / BKH;
    for (int it = 0; it < NIT; it++) {
        if (it + 1 < NIT) {
            int k = (it + 1) * BKH;
            uint32_t so = ((it + 1) & 1) * STAGE;
            CP_ASYNC_CG(da0 + so, Ap + k);
            CP_ASYNC_CG(da1 + so, Ap + (size_t)64 * K_ + k);
            CP_ASYNC_CG(db0 + so, Wp + k);
            CP_ASYNC_CG(db1 + so, Wp + (size_t)64 * K_ + k);
            CP_COMMIT();
            CP_WAIT(1);
        } else {
            CP_COMMIT();
            CP_WAIT(0);
        }
        __syncthreads();

        uint32_t sAs = sa + (it & 1) * STAGE;
        uint32_t sBs = sb + (it & 1) * STAGE;
#pragma unroll
        for (int ks = 0; ks < 2; ks++) {
            uint32_t af[2][4], bf[8][2];
#pragma unroll
            for (int mi = 0; mi < 2; mi++)
                ldsm_x4(af[mi][0], af[mi][1], af[mi][2], af[mi][3],
                        sAs + (uint32_t)((wm + mi * 16) * GSTR) * 2 + a_off + ks * 32);
#pragma unroll
            for (int nj = 0; nj < 4; nj++)
                ldsm_x4(bf[2 * nj][0], bf[2 * nj][1], bf[2 * nj + 1][0], bf[2 * nj + 1][1],
                        sBs + (uint32_t)((wn + nj * 16) * GSTR) * 2 + b_off + ks * 32);
#pragma unroll
            for (int mi = 0; mi < 2; mi++)
#pragma unroll
                for (int nj = 0; nj < 8; nj++)
                    mma_f16(c[mi][nj], af[mi], bf[nj]);
        }
        __syncthreads();
    }

#pragma unroll
    for (int mi = 0; mi < 2; mi++) {
#pragma unroll
        for (int nj = 0; nj < 8; nj++) {
            int m0 = bm + wm + mi * 16 + gid;
            int n0 = bn + wn + nj * 8 + 2 * tig;
            float b0v = bias[n0], b1v = bias[n0 + 1];
            size_t o = (size_t)m0 * G4 + n0;
            g_ih[o]                      = c[mi][nj][0] + b0v;
            g_ih[o + 1]                  = c[mi][nj][1] + b1v;
            g_ih[o + (size_t)8 * G4]     = c[mi][nj][2] + b0v;
            g_ih[o + (size_t)8 * G4 + 1] = c[mi][nj][3] + b1v;
        }
    }
}

// ---------------- zero h / barrier ----------------
__global__ void zero_state_kernel() {
    int i = blockIdx.x * blockDim.x + threadIdx.x;
    if (i < B_ * H_) {
        g_hA[i] = __float2half(0.f);
        g_hB[i] = __float2half(0.f);
    }
    if (i == 0) g_bar = 0u;
}

// ---------------- persistent recurrence kernel ----------------
// 8 warps = 2(m16) x 2(n16) x 2(k-half). Whole h staged per step in one shot
// via registers. Split grid barrier with hidden out-store + ih prefetch,
// warp-distributed spin.
#define WSTR 1032
#define HSTR 1032
#define PERSIST_SMEM ((32*WSTR + 32*HSTR) * 2 + 2 * 32 * 33 * 4)

__global__ __launch_bounds__(256, 1)
void lstm_persist_kernel(const float* __restrict__ Whh_raw, int outsel,
                         float* __restrict__ out_ext)
{
    extern __shared__ __half smh[];
    __half* Wsm = smh;                               // 32 x 1032 halves
    __half* Hsm = Wsm + 32 * WSTR;                   // 32 x 1032 halves
    float*  Ps  = (float*)(Hsm + 32 * HSTR);         // 2 x 32 x 33 floats

    int tid  = threadIdx.x;
    int warp = tid >> 5, lane = tid & 31;
    int gid  = lane >> 2, tig = lane & 3;
    int kh   = warp & 1;           // k-half
    int nj   = (warp >> 1) & 1;    // n16 tile
    int mi   = warp >> 2;          // m16 tile
    int j0   = blockIdx.x * 8;

    // ---- load Whh slice into SMEM once (fp16, gathered gate layout) ----
#pragma unroll 4
    for (int i = 0; i < 32; i++) {
        int idx = i * 256 + tid;
        int r   = idx >> 8;
        int c4  = idx & 255;
        int g   = r >> 3, jr = r & 7;
        const float4 v = *(const float4*)(Whh_raw + ((size_t)(g * H_ + j0 + jr)) * K_ + c4 * 4);
        *(__half2*)&Wsm[r * WSTR + c4 * 4]     = __floats2half2_rn(v.x, v.y);
        *(__half2*)&Wsm[r * WSTR + c4 * 4 + 2] = __floats2half2_rn(v.z, v.w);
    }

    uint32_t hs_base = (uint32_t)__cvta_generic_to_shared(Hsm);
    uint32_t ws_base = (uint32_t)__cvta_generic_to_shared(Wsm);
    uint32_t a_base = hs_base +
        (uint32_t)((mi * 16 + (lane & 7) + ((lane >> 3) & 1) * 8) * HSTR +
                   (lane >> 4) * 8 + kh * 512) * 2;
    uint32_t b_base = ws_base +
        (uint32_t)((nj * 16 + (lane & 7) + ((lane >> 4) & 1) * 8) * WSTR +
                   ((lane >> 3) & 1) * 8 + kh * 512) * 2;

    int hrow = tid >> 5;          // 0..7
    int hcol = lane * 8;          // halves
    int b    = tid >> 3;          // gate-math: batch
    int jj   = tid & 7;           // hidden col within slice
    float c_state = 0.f;
    float* Pk = Ps + kh * (32 * 33);

    __syncthreads();

    // preload ih for t=0
    size_t ihbase = ((size_t)b * T_) * G4 + j0 + jj;
    float ih0 = __ldcs(&g_ih[ihbase]);
    float ih1 = __ldcs(&g_ih[ihbase + H_]);
    float ih2 = __ldcs(&g_ih[ihbase + 2 * H_]);
    float ih3 = __ldcs(&g_ih[ihbase + 3 * H_]);

    for (int t = 0; t < T_; t++) {
        const __half* hin  = (t & 1) ? g_hB : g_hA;
        __half*       hout = (t & 1) ? g_hA : g_hB;

        // ---- stage whole h into SMEM (one shot, full MLP) ----
        uint4 rv[16];
#pragma unroll
        for (int p = 0; p < 4; p++)
#pragma unroll
            for (int q = 0; q < 4; q++)
                rv[p * 4 + q] = __ldcg((const uint4*)(hin + (size_t)(hrow + 8 * p) * H_ +
                                                       q * 256 + hcol));
#pragma unroll
        for (int p = 0; p < 4; p++)
#pragma unroll
            for (int q = 0; q < 4; q++)
                *(uint4*)&Hsm[(hrow + 8 * p) * HSTR + q * 256 + hcol] = rv[p * 4 + q];
        __syncthreads();

        // ---- mma: warp computes m16 x n16 over its k-half ----
        float acc0[4] = {0.f, 0.f, 0.f, 0.f};
        float acc1[4] = {0.f, 0.f, 0.f, 0.f};
        uint32_t aaddr = a_base, baddr = b_base;
#pragma unroll
        for (int ks = 0; ks < 32; ks++) {
            uint32_t af[4], bl[2], bhh[2];
            ldsm_x4(af[0], af[1], af[2], af[3], aaddr);
            ldsm_x4(bl[0], bl[1], bhh[0], bhh[1], baddr);
            mma_f16(acc0, af, bl);
            mma_f16(acc1, af, bhh);
            aaddr += 32;
            baddr += 32;
        }

        // scatter partial pre-activations (per k-half buffer)
        {
            int m = mi * 16 + gid;
            int n = nj * 16 + 2 * tig;
            Pk[m * 33 + n]               = acc0[0];
            Pk[m * 33 + n + 1]           = acc0[1];
            Pk[(m + 8) * 33 + n]         = acc0[2];
            Pk[(m + 8) * 33 + n + 1]     = acc0[3];
            Pk[m * 33 + n + 8]           = acc1[0];
            Pk[m * 33 + n + 9]           = acc1[1];
            Pk[(m + 8) * 33 + n + 8]     = acc1[2];
            Pk[(m + 8) * 33 + n + 9]     = acc1[3];
        }
        __syncthreads();

        // gate math: one (b, jj) per thread
        float hv;
        __half hr;
        {
            const float* P0 = Ps;
            const float* P1 = Ps + 32 * 33;
            float ipre = P0[b * 33 + jj]      + P1[b * 33 + jj]      + ih0;
            float fpre = P0[b * 33 + 8 + jj]  + P1[b * 33 + 8 + jj]  + ih1;
            float gpre = P0[b * 33 + 16 + jj] + P1[b * 33 + 16 + jj] + ih2;
            float opre = P0[b * 33 + 24 + jj] + P1[b * 33 + 24 + jj] + ih3;
            float iv = sig_f(ipre);
            float fv = sig_f(fpre);
            float gv = tanh_f(gpre);
            float ov = sig_f(opre);
            c_state = fv * c_state + iv * gv;
            hv = ov * tanh_f(c_state);
            hr = __float2half_rn(hv);
            unsigned short hb16 = __half_as_ushort(hr);
            asm volatile("st.global.cg.u16 [%0], %1;"
                         :: "l"(hout + b * H_ + j0 + jj), "h"(hb16) : "memory");
        }

        // ---- split grid barrier ----
        __threadfence();
        __syncthreads();                      // all hout stores fenced
        if (tid == 0) atomicAdd(&g_bar, 1u);  // arrive

        // hidden under the wait window: out store + next-step ih prefetch
        {
            size_t oidx = ((size_t)(b * T_ + t)) * H_ + j0 + jj;
            if (outsel) out_ext[oidx] = hv;
            else        g_y1h[oidx]   = hr;
            if (t + 1 < T_) {
                size_t ihn = ((size_t)(b * T_ + t + 1)) * G4 + j0 + jj;
                ih0 = __ldcs(&g_ih[ihn]);
                ih1 = __ldcs(&g_ih[ihn + H_]);
                ih2 = __ldcs(&g_ih[ihn + 2 * H_]);
                ih3 = __ldcs(&g_ih[ihn + 3 * H_]);
            }
        }

        // warp-distributed spin: lane 0 of each warp polls, then syncwarp.
        {
            unsigned target = (unsigned)NCTA * (unsigned)(t + 1);
            if (lane == 0) {
                unsigned v;
                do {
                    asm volatile("ld.acquire.gpu.global.u32 %0, [%1];"
                                 : "=r"(v) : "l"(&g_bar));
                } while (v < target);
            }
            __syncwarp();
        }
        // NOTE: no block-wide sync needed here — the post-stage __syncthreads
        // at the top of the next iteration orders Hsm writes vs all readers,
        // and Ps writes of the next step happen only after that sync.
    }
}

// ---------------- launch ----------------
extern "C" void kernel_launch(void* const* d_in, const int* in_sizes, int n_in,
                              void* d_out, int out_size) {
    const float* x    = (const float*)d_in[0];
    const float* Wih0 = (const float*)d_in[1];
    const float* Whh0 = (const float*)d_in[2];
    const float* b0   = (const float*)d_in[3];
    const float* Wih1 = (const float*)d_in[4];
    const float* Whh1 = (const float*)d_in[5];
    const float* b1   = (const float*)d_in[6];
    float* out = (float*)d_out;

    static int smem_set = 0;
    if (!smem_set) {
        cudaFuncSetAttribute(lstm_persist_kernel,
                             cudaFuncAttributeMaxDynamicSharedMemorySize, PERSIST_SMEM);
        smem_set = 1;
    }

    const int nx = M_ * K_;
    const int nw = G4 * K_;
    round_half_kernel<<<(nx / 4 + 255) / 256, 256>>>(x,    nx, 0);
    round_half_kernel<<<(nw / 4 + 255) / 256, 256>>>(Wih0, nw, 1);
    round_half_kernel<<<(nw / 4 + 255) / 256, 256>>>(Wih1, nw, 2);

    dim3 ggrid(G4 / BN, M_ / BM);   // (32, 64)

    // layer 0
    gemm_ih_kernel<<<ggrid, 256>>>(0, 0, b0);
    zero_state_kernel<<<(B_ * H_ + 1023) / 1024, 1024>>>();
    lstm_persist_kernel<<<NCTA, 256, PERSIST_SMEM>>>(Whh0, 0, nullptr);

    // layer 1
    gemm_ih_kernel<<<ggrid, 256>>>(1, 1, b1);
    zero_state_kernel<<<(B_ * H_ + 1023) / 1024, 1024>>>();
    lstm_persist_kernel<<<NCTA, 256, PERSIST_SMEM>>>(Whh1, 1, out);
}

// round 11
// speedup vs baseline: 1.4558x; 1.0126x over previous
#include <cuda_runtime.h>
#include <cuda_fp16.h>
#include <cstdint>
#include <math.h>

// Problem constants
#define B_  32
#define T_  256
#define H_  1024
#define G4  4096
#define K_  1024
#define M_  (B_*T_)       // 8192
#define NCTA 128

// ---------------- device scratch ----------------
__device__ __half g_xh [M_*K_];       // fp16 x
__device__ __half g_Wh [2*G4*K_];     // fp16 Wih0, Wih1
__device__ float  g_ih [M_*G4];       // input projection (fp32)
__device__ __half g_y1h[M_*H_];       // layer-0 output (fp16)
__device__ __half g_hA [B_*H_];
__device__ __half g_hB [B_*H_];
__device__ unsigned g_bar;

// ---------------- ptx helpers ----------------
__device__ __forceinline__ void mma_f16(float* c, const uint32_t* a, const uint32_t* b) {
    asm volatile(
        "mma.sync.aligned.m16n8k16.row.col.f32.f16.f16.f32 "
        "{%0,%1,%2,%3}, {%4,%5,%6,%7}, {%8,%9}, {%0,%1,%2,%3};\n"
        : "+f"(c[0]), "+f"(c[1]), "+f"(c[2]), "+f"(c[3])
        : "r"(a[0]), "r"(a[1]), "r"(a[2]), "r"(a[3]), "r"(b[0]), "r"(b[1]));
}

__device__ __forceinline__ void ldsm_x4(uint32_t& r0, uint32_t& r1, uint32_t& r2, uint32_t& r3,
                                        uint32_t addr) {
    asm volatile("ldmatrix.sync.aligned.m8n8.x4.shared.b16 {%0,%1,%2,%3}, [%4];"
                 : "=r"(r0), "=r"(r1), "=r"(r2), "=r"(r3) : "r"(addr));
}

#define CP_ASYNC_CG(dst, src) \
    asm volatile("cp.async.cg.shared.global [%0], [%1], 16;\n" :: "r"(dst), "l"(src))
#define CP_COMMIT() asm volatile("cp.async.commit_group;\n" ::: "memory")
#define CP_WAIT(N)  asm volatile("cp.async.wait_group %0;\n" :: "n"(N) : "memory")

__device__ __forceinline__ float sig_f(float x) {
    return __fdividef(1.f, 1.f + __expf(-x));
}
__device__ __forceinline__ float tanh_f(float x) {
    float e = __expf(2.f * x);
    return 1.f - __fdividef(2.f, e + 1.f);
}

// ---------------- fp32 -> fp16 conversion ----------------
__global__ void round_half_kernel(const float* __restrict__ src, int n, int dsel) {
    __half* dst = (dsel == 0) ? g_xh : (g_Wh + (size_t)(dsel - 1) * (G4 * K_));
    int i4 = (blockIdx.x * blockDim.x + threadIdx.x) * 4;
    if (i4 < n) {
        float4 v = *(const float4*)(src + i4);
        *(__half2*)(dst + i4)     = __floats2half2_rn(v.x, v.y);
        *(__half2*)(dst + i4 + 2) = __floats2half2_rn(v.z, v.w);
    }
}

// ---------------- input projection GEMM: 3-stage cp.async pipeline ----------------
#define BM 128
#define BN 128
#define BKH 32
#define GSTR 40
#define ASZ (BM * GSTR * 2)              // bytes per stage (10240)
#define GSMEM (3 * 2 * ASZ)              // 61440 bytes

__global__ __launch_bounds__(256, 2)
void gemm_ih_kernel(int asel, int woff, const float* __restrict__ bias) {
    const __half* A = asel ? g_y1h : g_xh;
    const __half* W = g_Wh + (size_t)woff * (G4 * K_);

    extern __shared__ __half gsm[];
    uint32_t sa = (uint32_t)__cvta_generic_to_shared(gsm);            // 3 A stages
    uint32_t sb = sa + 3 * ASZ;                                        // 3 B stages

    int tid  = threadIdx.x;
    int bm   = blockIdx.y * BM;
    int bn   = blockIdx.x * BN;
    int warp = tid >> 5, lane = tid & 31;
    int gid  = lane >> 2, tig = lane & 3;
    int wm   = (warp & 3) * 32;
    int wn   = (warp >> 2) * 64;

    int r0   = tid >> 2;
    int gcol = (tid & 3) * 8;
    const __half* Ap = A + (size_t)(bm + r0) * K_ + gcol;
    const __half* Wp = W + (size_t)(bn + r0) * K_ + gcol;
    uint32_t da0 = sa + (uint32_t)(r0 * GSTR + gcol) * 2;
    uint32_t da1 = sa + (uint32_t)((r0 + 64) * GSTR + gcol) * 2;
    uint32_t db0 = sb + (uint32_t)(r0 * GSTR + gcol) * 2;
    uint32_t db1 = sb + (uint32_t)((r0 + 64) * GSTR + gcol) * 2;

    uint32_t a_off = (uint32_t)(((lane & 7) + ((lane >> 3) & 1) * 8) * GSTR + (lane >> 4) * 8) * 2;
    uint32_t b_off = (uint32_t)(((lane & 7) + ((lane >> 4) & 1) * 8) * GSTR + ((lane >> 3) & 1) * 8) * 2;

    float c[2][8][4];
#pragma unroll
    for (int i = 0; i < 2; i++)
#pragma unroll
        for (int j = 0; j < 8; j++)
#pragma unroll
            for (int q = 0; q < 4; q++) c[i][j][q] = 0.f;

#define G_LOAD(it, stg_)                                                      \
    do {                                                                      \
        int k_ = (it) * BKH;                                                  \
        uint32_t so_ = (uint32_t)(stg_) * ASZ;                                \
        CP_ASYNC_CG(da0 + so_, Ap + k_);                                      \
        CP_ASYNC_CG(da1 + so_, Ap + (size_t)64 * K_ + k_);                    \
        CP_ASYNC_CG(db0 + so_, Wp + k_);                                      \
        CP_ASYNC_CG(db1 + so_, Wp + (size_t)64 * K_ + k_);                    \
        CP_COMMIT();                                                          \
    } while (0)

    const int NIT = K_ / BKH;   // 32
    G_LOAD(0, 0);               // group g0 -> stage 0
    G_LOAD(1, 1);               // group g1 -> stage 1

    int stg = 0;
    for (int it = 0; it < NIT; it++) {
        // ensure group g_it (-> stage stg) has landed.
        // pending before wait: {g_it, g_{it+1}} (2) except last iter: {g_it} (1).
        if (it == NIT - 1) CP_WAIT(0);
        else               CP_WAIT(1);
        __syncthreads();   // all threads: g_it visible AND done reading stage (stg+2)%3

        if (it + 2 < NIT) {
            int nst = stg + 2; if (nst >= 3) nst -= 3;
            G_LOAD(it + 2, nst);
        }

        uint32_t sAs = sa + (uint32_t)stg * ASZ;
        uint32_t sBs = sb + (uint32_t)stg * ASZ;
#pragma unroll
        for (int ks = 0; ks < 2; ks++) {
            uint32_t af[2][4], bf[8][2];
#pragma unroll
            for (int mi = 0; mi < 2; mi++)
                ldsm_x4(af[mi][0], af[mi][1], af[mi][2], af[mi][3],
                        sAs + (uint32_t)((wm + mi * 16) * GSTR) * 2 + a_off + ks * 32);
#pragma unroll
            for (int nj = 0; nj < 4; nj++)
                ldsm_x4(bf[2 * nj][0], bf[2 * nj][1], bf[2 * nj + 1][0], bf[2 * nj + 1][1],
                        sBs + (uint32_t)((wn + nj * 16) * GSTR) * 2 + b_off + ks * 32);
#pragma unroll
            for (int mi = 0; mi < 2; mi++)
#pragma unroll
                for (int nj = 0; nj < 8; nj++)
                    mma_f16(c[mi][nj], af[mi], bf[nj]);
        }
        if (++stg >= 3) stg = 0;
    }
#undef G_LOAD

#pragma unroll
    for (int mi = 0; mi < 2; mi++) {
#pragma unroll
        for (int nj = 0; nj < 8; nj++) {
            int m0 = bm + wm + mi * 16 + gid;
            int n0 = bn + wn + nj * 8 + 2 * tig;
            float b0v = bias[n0], b1v = bias[n0 + 1];
            size_t o = (size_t)m0 * G4 + n0;
            g_ih[o]                      = c[mi][nj][0] + b0v;
            g_ih[o + 1]                  = c[mi][nj][1] + b1v;
            g_ih[o + (size_t)8 * G4]     = c[mi][nj][2] + b0v;
            g_ih[o + (size_t)8 * G4 + 1] = c[mi][nj][3] + b1v;
        }
    }
}

// ---------------- zero h / barrier ----------------
__global__ void zero_state_kernel() {
    int i = blockIdx.x * blockDim.x + threadIdx.x;
    if (i < B_ * H_) {
        g_hA[i] = __float2half(0.f);
        g_hB[i] = __float2half(0.f);
    }
    if (i == 0) g_bar = 0u;
}

// ---------------- persistent recurrence kernel (R8 winner, unchanged) ----------------
#define WSTR 1032
#define HSTR 1032
#define PERSIST_SMEM ((32*WSTR + 32*HSTR) * 2 + 2 * 32 * 33 * 4)

__global__ __launch_bounds__(256, 1)
void lstm_persist_kernel(const float* __restrict__ Whh_raw, int outsel,
                         float* __restrict__ out_ext)
{
    extern __shared__ __half smh[];
    __half* Wsm = smh;
    __half* Hsm = Wsm + 32 * WSTR;
    float*  Ps  = (float*)(Hsm + 32 * HSTR);

    int tid  = threadIdx.x;
    int warp = tid >> 5, lane = tid & 31;
    int gid  = lane >> 2, tig = lane & 3;
    int kh   = warp & 1;
    int nj   = (warp >> 1) & 1;
    int mi   = warp >> 2;
    int j0   = blockIdx.x * 8;

#pragma unroll 4
    for (int i = 0; i < 32; i++) {
        int idx = i * 256 + tid;
        int r   = idx >> 8;
        int c4  = idx & 255;
        int g   = r >> 3, jr = r & 7;
        const float4 v = *(const float4*)(Whh_raw + ((size_t)(g * H_ + j0 + jr)) * K_ + c4 * 4);
        *(__half2*)&Wsm[r * WSTR + c4 * 4]     = __floats2half2_rn(v.x, v.y);
        *(__half2*)&Wsm[r * WSTR + c4 * 4 + 2] = __floats2half2_rn(v.z, v.w);
    }

    uint32_t hs_base = (uint32_t)__cvta_generic_to_shared(Hsm);
    uint32_t ws_base = (uint32_t)__cvta_generic_to_shared(Wsm);
    uint32_t a_base = hs_base +
        (uint32_t)((mi * 16 + (lane & 7) + ((lane >> 3) & 1) * 8) * HSTR +
                   (lane >> 4) * 8 + kh * 512) * 2;
    uint32_t b_base = ws_base +
        (uint32_t)((nj * 16 + (lane & 7) + ((lane >> 4) & 1) * 8) * WSTR +
                   ((lane >> 3) & 1) * 8 + kh * 512) * 2;

    int hrow = tid >> 5;
    int hcol = lane * 8;
    int b    = tid >> 3;
    int jj   = tid & 7;
    float c_state = 0.f;
    float* Pk = Ps + kh * (32 * 33);

    __syncthreads();

    size_t ihbase = ((size_t)b * T_) * G4 + j0 + jj;
    float ih0 = __ldcs(&g_ih[ihbase]);
    float ih1 = __ldcs(&g_ih[ihbase + H_]);
    float ih2 = __ldcs(&g_ih[ihbase + 2 * H_]);
    float ih3 = __ldcs(&g_ih[ihbase + 3 * H_]);

    for (int t = 0; t < T_; t++) {
        const __half* hin  = (t & 1) ? g_hB : g_hA;
        __half*       hout = (t & 1) ? g_hA : g_hB;

        uint4 rv[16];
#pragma unroll
        for (int p = 0; p < 4; p++)
#pragma unroll
            for (int q = 0; q < 4; q++)
                rv[p * 4 + q] = __ldcg((const uint4*)(hin + (size_t)(hrow + 8 * p) * H_ +
                                                       q * 256 + hcol));
#pragma unroll
        for (int p = 0; p < 4; p++)
#pragma unroll
            for (int q = 0; q < 4; q++)
                *(uint4*)&Hsm[(hrow + 8 * p) * HSTR + q * 256 + hcol] = rv[p * 4 + q];
        __syncthreads();

        float acc0[4] = {0.f, 0.f, 0.f, 0.f};
        float acc1[4] = {0.f, 0.f, 0.f, 0.f};
        uint32_t aaddr = a_base, baddr = b_base;
#pragma unroll
        for (int ks = 0; ks < 32; ks++) {
            uint32_t af[4], bl[2], bhh[2];
            ldsm_x4(af[0], af[1], af[2], af[3], aaddr);
            ldsm_x4(bl[0], bl[1], bhh[0], bhh[1], baddr);
            mma_f16(acc0, af, bl);
            mma_f16(acc1, af, bhh);
            aaddr += 32;
            baddr += 32;
        }

        {
            int m = mi * 16 + gid;
            int n = nj * 16 + 2 * tig;
            Pk[m * 33 + n]               = acc0[0];
            Pk[m * 33 + n + 1]           = acc0[1];
            Pk[(m + 8) * 33 + n]         = acc0[2];
            Pk[(m + 8) * 33 + n + 1]     = acc0[3];
            Pk[m * 33 + n + 8]           = acc1[0];
            Pk[m * 33 + n + 9]           = acc1[1];
            Pk[(m + 8) * 33 + n + 8]     = acc1[2];
            Pk[(m + 8) * 33 + n + 9]     = acc1[3];
        }
        __syncthreads();

        float hv;
        __half hr;
        {
            const float* P0 = Ps;
            const float* P1 = Ps + 32 * 33;
            float ipre = P0[b * 33 + jj]      + P1[b * 33 + jj]      + ih0;
            float fpre = P0[b * 33 + 8 + jj]  + P1[b * 33 + 8 + jj]  + ih1;
            float gpre = P0[b * 33 + 16 + jj] + P1[b * 33 + 16 + jj] + ih2;
            float opre = P0[b * 33 + 24 + jj] + P1[b * 33 + 24 + jj] + ih3;
            float iv = sig_f(ipre);
            float fv = sig_f(fpre);
            float gv = tanh_f(gpre);
            float ov = sig_f(opre);
            c_state = fv * c_state + iv * gv;
            hv = ov * tanh_f(c_state);
            hr = __float2half_rn(hv);
            unsigned short hb16 = __half_as_ushort(hr);
            asm volatile("st.global.cg.u16 [%0], %1;"
                         :: "l"(hout + b * H_ + j0 + jj), "h"(hb16) : "memory");
        }

        __threadfence();
        __syncthreads();
        if (tid == 0) atomicAdd(&g_bar, 1u);

        {
            size_t oidx = ((size_t)(b * T_ + t)) * H_ + j0 + jj;
            if (outsel) out_ext[oidx] = hv;
            else        g_y1h[oidx]   = hr;
            if (t + 1 < T_) {
                size_t ihn = ((size_t)(b * T_ + t + 1)) * G4 + j0 + jj;
                ih0 = __ldcs(&g_ih[ihn]);
                ih1 = __ldcs(&g_ih[ihn + H_]);
                ih2 = __ldcs(&g_ih[ihn + 2 * H_]);
                ih3 = __ldcs(&g_ih[ihn + 3 * H_]);
            }
        }

        {
            unsigned target = (unsigned)NCTA * (unsigned)(t + 1);
            if (lane == 0) {
                unsigned v;
                do {
                    asm volatile("ld.acquire.gpu.global.u32 %0, [%1];"
                                 : "=r"(v) : "l"(&g_bar));
                } while (v < target);
            }
            __syncwarp();
        }
    }
}

// ---------------- launch ----------------
extern "C" void kernel_launch(void* const* d_in, const int* in_sizes, int n_in,
                              void* d_out, int out_size) {
    const float* x    = (const float*)d_in[0];
    const float* Wih0 = (const float*)d_in[1];
    const float* Whh0 = (const float*)d_in[2];
    const float* b0   = (const float*)d_in[3];
    const float* Wih1 = (const float*)d_in[4];
    const float* Whh1 = (const float*)d_in[5];
    const float* b1   = (const float*)d_in[6];
    float* out = (float*)d_out;

    static int attr_set = 0;
    if (!attr_set) {
        cudaFuncSetAttribute(lstm_persist_kernel,
                             cudaFuncAttributeMaxDynamicSharedMemorySize, PERSIST_SMEM);
        cudaFuncSetAttribute(gemm_ih_kernel,
                             cudaFuncAttributeMaxDynamicSharedMemorySize, GSMEM);
        attr_set = 1;
    }

    const int nx = M_ * K_;
    const int nw = G4 * K_;
    round_half_kernel<<<(nx / 4 + 255) / 256, 256>>>(x,    nx, 0);
    round_half_kernel<<<(nw / 4 + 255) / 256, 256>>>(Wih0, nw, 1);
    round_half_kernel<<<(nw / 4 + 255) / 256, 256>>>(Wih1, nw, 2);

    dim3 ggrid(G4 / BN, M_ / BM);   // (32, 64)

    // layer 0
    gemm_ih_kernel<<<ggrid, 256, GSMEM>>>(0, 0, b0);
    zero_state_kernel<<<(B_ * H_ + 1023) / 1024, 1024>>>();
    lstm_persist_kernel<<<NCTA, 256, PERSIST_SMEM>>>(Whh0, 0, nullptr);

    // layer 1
    gemm_ih_kernel<<<ggrid, 256, GSMEM>>>(1, 1, b1);
    zero_state_kernel<<<(B_ * H_ + 1023) / 1024, 1024>>>();
    lstm_persist_kernel<<<NCTA, 256, PERSIST_SMEM>>>(Whh1, 1, out);
}